// round 3
// baseline (speedup 1.0000x reference)
#include <cuda_runtime.h>

// DenseRNN: B=256, T=1024, D=128, H=128, fp32. out = final Elman state [B,H].
//
// 128 CTAs x 512 threads (16 warps). CTA owns batch rows (2b, 2b+1).
// Thread = (col = warp*8 + lane%8, quarter q = lane/8 -> k-slice of 32).
// Weights (both matrices, 32-elem k-slice of column `col`) live in registers
// as packed f32x2; math uses fma.rn.f32x2. Quarter partials reduced with
// shfl_xor(8), shfl_xor(16). Single __syncthreads per step via full double
// buffering of x and state. tanh via ex2.approx + rcp.approx (~1e-6 err).
//
// Shared slices are padded (+4 words per 32) so the 4 quarter base addresses
// fall in distinct banks -> conflict-free LDS.128 with 8-lane broadcast.

#define Bn 256
#define Tn 1024
#define Dn 128
#define Hn 128

typedef unsigned long long u64;
struct alignas(16) f4 { u64 a, b; };   // 4 floats as 2 packed pairs

__device__ __forceinline__ u64 pk2(float lo, float hi) {
    u64 r; asm("mov.b64 %0, {%1, %2};" : "=l"(r) : "f"(lo), "f"(hi)); return r;
}
__device__ __forceinline__ void upk2(u64 v, float& lo, float& hi) {
    asm("mov.b64 {%0, %1}, %2;" : "=f"(lo), "=f"(hi) : "l"(v));
}
__device__ __forceinline__ u64 ffma2(u64 a, u64 b, u64 c) {
    u64 d; asm("fma.rn.f32x2 %0, %1, %2, %3;" : "=l"(d) : "l"(a), "l"(b), "l"(c));
    return d;
}
__device__ __forceinline__ u64 fadd2(u64 a, u64 b) {
    u64 d; asm("add.rn.f32x2 %0, %1, %2;" : "=l"(d) : "l"(a), "l"(b));
    return d;
}
// tanh(x) = 1 - 2/(exp2(2x*log2e)+1); MUFU.EX2 + MUFU.RCP, ~1e-6 rel err.
__device__ __forceinline__ float fast_tanh(float x) {
    float e;
    asm("ex2.approx.f32 %0, %1;" : "=f"(e) : "f"(x * 2.885390081777927f));
    float r;
    asm("rcp.approx.f32 %0, %1;" : "=f"(r) : "f"(e + 1.0f));
    return fmaf(-2.0f, r, 1.0f);
}

// padded word index: +4 words of pad after every 32 words
#define PW(e) ((e) + (((e) >> 5) << 2))
#define ROWW 144   // padded words per 128-float row vector (last used word 139)

__global__ __launch_bounds__(512, 1)
void rnn_fused(const float* __restrict__ x,      // [B,T,D]
               const float* __restrict__ w,      // [D,H]
               const float* __restrict__ Wr,     // [H,H]
               const float* __restrict__ bias,   // [H]
               float* __restrict__ out)          // [B,H]
{
    __shared__ alignas(16) float sx[2][2][ROWW];  // [buf][row][padded word]
    __shared__ alignas(16) float ss[2][2][ROWW];

    const int tid  = threadIdx.x;
    const int lane = tid & 31;
    const int warp = tid >> 5;
    const int col  = (warp << 3) | (lane & 7);   // 0..127
    const int q    = lane >> 3;                  // 0..3 -> k slice q*32..q*32+31
    const int q36  = q * 36;                     // padded word base of slice
    const int row0 = blockIdx.x * 2;
    const int pcol = PW(col);

    // ---- weights: 32-element k-slice of column `col`, both matrices ----
    u64 wp[16], Wp[16];
    #pragma unroll
    for (int i = 0; i < 16; i++) {
        int k = q * 32 + 2 * i;
        wp[i] = pk2(w [(size_t)k * Hn + col], w [(size_t)(k + 1) * Hn + col]);
        Wp[i] = pk2(Wr[(size_t)k * Hn + col], Wr[(size_t)(k + 1) * Hn + col]);
    }
    const float bcol = bias[col];

    // ---- x streaming role: warps 0-7 stream x elements ----
    const int xrow = tid >> 7;                   // valid when tid<256
    const int xd   = tid & 127;
    const int pxd  = PW(xd);
    const float* xp = x + ((size_t)(row0 + (xrow & 1)) * Tn) * Dn + xd;

    // slice base pointers (f4 units; row stride = 36 f4)
    const f4* xb0 = (const f4*)&sx[0][0][q36];
    const f4* xb1 = (const f4*)&sx[1][0][q36];
    const f4* sb0 = (const f4*)&ss[0][0][q36];
    const f4* sb1 = (const f4*)&ss[1][0][q36];

    float y0, y1;

    // ================= t = 0 : state0 = tanh(x0@w + b) =================
    if (tid < 256) sx[0][xrow][pxd] = xp[0];
    __syncthreads();
    {
        u64 a0 = 0, b0 = 0, a1 = 0, b1 = 0;
        #pragma unroll
        for (int i = 0; i < 8; i++) {
            f4 v0 = xb0[i];
            f4 v1 = xb0[i + 36];
            a0 = ffma2(v0.a, wp[2*i],   a0);
            b0 = ffma2(v0.b, wp[2*i+1], b0);
            a1 = ffma2(v1.a, wp[2*i],   a1);
            b1 = ffma2(v1.b, wp[2*i+1], b1);
        }
        float lo, hi;
        u64 c0 = fadd2(a0, b0), c1 = fadd2(a1, b1);
        upk2(c0, lo, hi); float s0 = lo + hi;
        upk2(c1, lo, hi); float s1 = lo + hi;
        s0 += __shfl_xor_sync(0xffffffffu, s0, 8);
        s0 += __shfl_xor_sync(0xffffffffu, s0, 16);
        s1 += __shfl_xor_sync(0xffffffffu, s1, 8);
        s1 += __shfl_xor_sync(0xffffffffu, s1, 16);
        y0 = fast_tanh(s0 + bcol);
        y1 = fast_tanh(s1 + bcol);
        if (q == 0) { ss[0][0][pcol] = y0; ss[0][1][pcol] = y1; }
        if (tid < 256) sx[1][xrow][pxd] = xp[Dn];
    }
    __syncthreads();

    // ================= t = 1 .. T-1 ====================================
    // step t: read sx[t&1], ss[(t-1)&1]; write sx[(t+1)&1], ss[t&1]; 1 bar.
    const float* xq = xp + 2 * Dn;   // points at x[t+1] element when t=1
    #pragma unroll 2
    for (int t = 1; t < Tn; t++) {
        float xnext = 0.0f;
        if (tid < 256 && t + 1 < Tn) xnext = *xq;
        xq += Dn;

        const f4* xv = (t & 1) ? xb1 : xb0;
        const f4* sv = ((t - 1) & 1) ? sb1 : sb0;

        u64 a0 = 0, b0 = 0, a1 = 0, b1 = 0;
        #pragma unroll
        for (int i = 0; i < 8; i++) {
            f4 s0v = sv[i];
            f4 s1v = sv[i + 36];
            a0 = ffma2(s0v.a, Wp[2*i],   a0);
            b0 = ffma2(s0v.b, Wp[2*i+1], b0);
            a1 = ffma2(s1v.a, Wp[2*i],   a1);
            b1 = ffma2(s1v.b, Wp[2*i+1], b1);
        }
        #pragma unroll
        for (int i = 0; i < 8; i++) {
            f4 x0v = xv[i];
            f4 x1v = xv[i + 36];
            a0 = ffma2(x0v.a, wp[2*i],   a0);
            b0 = ffma2(x0v.b, wp[2*i+1], b0);
            a1 = ffma2(x1v.a, wp[2*i],   a1);
            b1 = ffma2(x1v.b, wp[2*i+1], b1);
        }

        float lo, hi;
        u64 c0 = fadd2(a0, b0), c1 = fadd2(a1, b1);
        upk2(c0, lo, hi); float s0 = lo + hi;
        upk2(c1, lo, hi); float s1 = lo + hi;
        s0 += __shfl_xor_sync(0xffffffffu, s0, 8);
        s0 += __shfl_xor_sync(0xffffffffu, s0, 16);
        s1 += __shfl_xor_sync(0xffffffffu, s1, 8);
        s1 += __shfl_xor_sync(0xffffffffu, s1, 16);
        y0 = fast_tanh(s0 + bcol);
        y1 = fast_tanh(s1 + bcol);

        float* sw = &ss[t & 1][0][0];
        if (q == 0) { sw[pcol] = y0; sw[ROWW + pcol] = y1; }
        if (tid < 256) sx[(t + 1) & 1][xrow][pxd] = xnext;
        __syncthreads();
    }

    // ---- final state (registers hold last y) ----
    if (q == 0) {
        out[(size_t)row0 * Hn + col]       = y0;
        out[(size_t)(row0 + 1) * Hn + col] = y1;
    }
}

extern "C" void kernel_launch(void* const* d_in, const int* in_sizes, int n_in,
                              void* d_out, int out_size)
{
    const float* x    = (const float*)d_in[0];  // [256,1024,128]
    const float* w    = (const float*)d_in[1];  // [128,128]
    const float* Wr   = (const float*)d_in[2];  // [128,128]
    const float* bias = (const float*)d_in[3];  // [128]
    float* out = (float*)d_out;                 // [256,128]

    rnn_fused<<<Bn / 2, 512>>>(x, w, Wr, bias, out);
}

// round 4
// speedup vs baseline: 1.0023x; 1.0023x over previous
#include <cuda_runtime.h>

// DenseRNN: B=256, T=1024, D=128, H=128, fp32. out = final Elman state [B,H].
//
// 128 CTAs x 512 threads (16 warps). CTA owns batch rows (2b, 2b+1).
// Thread = (col = warp*8 + lane%8, quarter q = lane/8 -> k-slice of 32).
// Weights (both matrices, 32-elem k-slice of column `col`) live in registers
// as packed f32x2; math uses fma.rn.f32x2. Quarter partials reduced with
// shfl_xor(8), shfl_xor(16). Single __syncthreads per step via full double
// buffering of x and state. tanh via ex2.approx + rcp.approx (~1e-6 err).
//
// Shared slices are padded (+4 words per 32) so the 4 quarter base addresses
// fall in distinct banks -> conflict-free LDS.128 with 8-lane broadcast.

#define Bn 256
#define Tn 1024
#define Dn 128
#define Hn 128

typedef unsigned long long u64;
struct alignas(16) f4 { u64 a, b; };   // 4 floats as 2 packed pairs

__device__ __forceinline__ u64 pk2(float lo, float hi) {
    u64 r; asm("mov.b64 %0, {%1, %2};" : "=l"(r) : "f"(lo), "f"(hi)); return r;
}
__device__ __forceinline__ void upk2(u64 v, float& lo, float& hi) {
    asm("mov.b64 {%0, %1}, %2;" : "=f"(lo), "=f"(hi) : "l"(v));
}
__device__ __forceinline__ u64 ffma2(u64 a, u64 b, u64 c) {
    u64 d; asm("fma.rn.f32x2 %0, %1, %2, %3;" : "=l"(d) : "l"(a), "l"(b), "l"(c));
    return d;
}
__device__ __forceinline__ u64 fadd2(u64 a, u64 b) {
    u64 d; asm("add.rn.f32x2 %0, %1, %2;" : "=l"(d) : "l"(a), "l"(b));
    return d;
}
// tanh(x) = 1 - 2/(exp2(2x*log2e)+1); MUFU.EX2 + MUFU.RCP, ~1e-6 rel err.
__device__ __forceinline__ float fast_tanh(float x) {
    float e;
    asm("ex2.approx.f32 %0, %1;" : "=f"(e) : "f"(x * 2.885390081777927f));
    float r;
    asm("rcp.approx.f32 %0, %1;" : "=f"(r) : "f"(e + 1.0f));
    return fmaf(-2.0f, r, 1.0f);
}

// padded word index: +4 words of pad after every 32 words
#define PW(e) ((e) + (((e) >> 5) << 2))
#define ROWW 144   // padded words per 128-float row vector (last used word 139)

__global__ __launch_bounds__(512, 1)
void rnn_fused(const float* __restrict__ x,      // [B,T,D]
               const float* __restrict__ w,      // [D,H]
               const float* __restrict__ Wr,     // [H,H]
               const float* __restrict__ bias,   // [H]
               float* __restrict__ out)          // [B,H]
{
    __shared__ alignas(16) float sx[2][2][ROWW];  // [buf][row][padded word]
    __shared__ alignas(16) float ss[2][2][ROWW];

    const int tid  = threadIdx.x;
    const int lane = tid & 31;
    const int warp = tid >> 5;
    const int col  = (warp << 3) | (lane & 7);   // 0..127
    const int q    = lane >> 3;                  // 0..3 -> k slice q*32..q*32+31
    const int q36  = q * 36;                     // padded word base of slice
    const int row0 = blockIdx.x * 2;
    const int pcol = PW(col);

    // ---- weights: 32-element k-slice of column `col`, both matrices ----
    u64 wp[16], Wp[16];
    #pragma unroll
    for (int i = 0; i < 16; i++) {
        int k = q * 32 + 2 * i;
        wp[i] = pk2(w [(size_t)k * Hn + col], w [(size_t)(k + 1) * Hn + col]);
        Wp[i] = pk2(Wr[(size_t)k * Hn + col], Wr[(size_t)(k + 1) * Hn + col]);
    }
    const float bcol = bias[col];

    // ---- x streaming role: warps 0-7 stream x elements ----
    const int xrow = tid >> 7;                   // valid when tid<256
    const int xd   = tid & 127;
    const int pxd  = PW(xd);
    const float* xp = x + ((size_t)(row0 + (xrow & 1)) * Tn) * Dn + xd;

    // slice base pointers (f4 units; row stride = 36 f4)
    const f4* xb0 = (const f4*)&sx[0][0][q36];
    const f4* xb1 = (const f4*)&sx[1][0][q36];
    const f4* sb0 = (const f4*)&ss[0][0][q36];
    const f4* sb1 = (const f4*)&ss[1][0][q36];

    float y0, y1;

    // ================= t = 0 : state0 = tanh(x0@w + b) =================
    if (tid < 256) sx[0][xrow][pxd] = xp[0];
    __syncthreads();
    {
        u64 a0 = 0, b0 = 0, a1 = 0, b1 = 0;
        #pragma unroll
        for (int i = 0; i < 8; i++) {
            f4 v0 = xb0[i];
            f4 v1 = xb0[i + 36];
            a0 = ffma2(v0.a, wp[2*i],   a0);
            b0 = ffma2(v0.b, wp[2*i+1], b0);
            a1 = ffma2(v1.a, wp[2*i],   a1);
            b1 = ffma2(v1.b, wp[2*i+1], b1);
        }
        float lo, hi;
        u64 c0 = fadd2(a0, b0), c1 = fadd2(a1, b1);
        upk2(c0, lo, hi); float s0 = lo + hi;
        upk2(c1, lo, hi); float s1 = lo + hi;
        s0 += __shfl_xor_sync(0xffffffffu, s0, 8);
        s0 += __shfl_xor_sync(0xffffffffu, s0, 16);
        s1 += __shfl_xor_sync(0xffffffffu, s1, 8);
        s1 += __shfl_xor_sync(0xffffffffu, s1, 16);
        y0 = fast_tanh(s0 + bcol);
        y1 = fast_tanh(s1 + bcol);
        if (q == 0) { ss[0][0][pcol] = y0; ss[0][1][pcol] = y1; }
        if (tid < 256) sx[1][xrow][pxd] = xp[Dn];
    }
    __syncthreads();

    // ================= t = 1 .. T-1 ====================================
    // step t: read sx[t&1], ss[(t-1)&1]; write sx[(t+1)&1], ss[t&1]; 1 bar.
    const float* xq = xp + 2 * Dn;   // points at x[t+1] element when t=1
    #pragma unroll 2
    for (int t = 1; t < Tn; t++) {
        float xnext = 0.0f;
        if (tid < 256 && t + 1 < Tn) xnext = *xq;
        xq += Dn;

        const f4* xv = (t & 1) ? xb1 : xb0;
        const f4* sv = ((t - 1) & 1) ? sb1 : sb0;

        u64 a0 = 0, b0 = 0, a1 = 0, b1 = 0;
        #pragma unroll
        for (int i = 0; i < 8; i++) {
            f4 s0v = sv[i];
            f4 s1v = sv[i + 36];
            a0 = ffma2(s0v.a, Wp[2*i],   a0);
            b0 = ffma2(s0v.b, Wp[2*i+1], b0);
            a1 = ffma2(s1v.a, Wp[2*i],   a1);
            b1 = ffma2(s1v.b, Wp[2*i+1], b1);
        }
        #pragma unroll
        for (int i = 0; i < 8; i++) {
            f4 x0v = xv[i];
            f4 x1v = xv[i + 36];
            a0 = ffma2(x0v.a, wp[2*i],   a0);
            b0 = ffma2(x0v.b, wp[2*i+1], b0);
            a1 = ffma2(x1v.a, wp[2*i],   a1);
            b1 = ffma2(x1v.b, wp[2*i+1], b1);
        }

        float lo, hi;
        u64 c0 = fadd2(a0, b0), c1 = fadd2(a1, b1);
        upk2(c0, lo, hi); float s0 = lo + hi;
        upk2(c1, lo, hi); float s1 = lo + hi;
        s0 += __shfl_xor_sync(0xffffffffu, s0, 8);
        s0 += __shfl_xor_sync(0xffffffffu, s0, 16);
        s1 += __shfl_xor_sync(0xffffffffu, s1, 8);
        s1 += __shfl_xor_sync(0xffffffffu, s1, 16);
        y0 = fast_tanh(s0 + bcol);
        y1 = fast_tanh(s1 + bcol);

        float* sw = &ss[t & 1][0][0];
        if (q == 0) { sw[pcol] = y0; sw[ROWW + pcol] = y1; }
        if (tid < 256) sx[(t + 1) & 1][xrow][pxd] = xnext;
        __syncthreads();
    }

    // ---- final state (registers hold last y) ----
    if (q == 0) {
        out[(size_t)row0 * Hn + col]       = y0;
        out[(size_t)(row0 + 1) * Hn + col] = y1;
    }
}

extern "C" void kernel_launch(void* const* d_in, const int* in_sizes, int n_in,
                              void* d_out, int out_size)
{
    const float* x    = (const float*)d_in[0];  // [256,1024,128]
    const float* w    = (const float*)d_in[1];  // [128,128]
    const float* Wr   = (const float*)d_in[2];  // [128,128]
    const float* bias = (const float*)d_in[3];  // [128]
    float* out = (float*)d_out;                 // [256,128]

    rnn_fused<<<Bn / 2, 512>>>(x, w, Wr, bias, out);
}